// round 5
// baseline (speedup 1.0000x reference)
#include <cuda_runtime.h>
#include <cuda_fp16.h>
#include <cstdint>
#include <math.h>

// ---------------------------------------------------------------------------
// Problem constants
// ---------------------------------------------------------------------------
#define Nn 16
#define Hh 112
#define Wd 112
#define Cc 128
#define Ho 110
#define Wo 110
#define Co 256
#define KK 1152                 // 3*3*128
#define MM (Nn*Ho*Wo)           // 193600
#define PIX (Nn*Hh*Wd)          // 200704
#define XELT (PIX*Cc)           // 25,690,112
#define FIXCAP (1u << 21)
#define TAU 1e-5f

// ---------------------------------------------------------------------------
// Scratch (device globals; no allocations allowed)
// ---------------------------------------------------------------------------
__device__ float g_s[PIX];
__device__ float g_xni[MM];
__device__ float g_ws[Co];
__device__ float g_ae[Co];
__device__ __half g_Ah[XELT];        // x hi (fp16)
__device__ __half g_Al[XELT];        // x lo (fp16)
__device__ __half g_Bh[Co * KK];     // W hi, [n][k]
__device__ __half g_Bl[Co * KK];     // W lo, [n][k]
__device__ float  g_WT[Co * KK];     // W fp32 [n][k] (fixup)
__device__ uint32_t g_fix_list[FIXCAP];
__device__ uint32_t g_fix_cnt;

// ---------------------------------------------------------------------------
// Helpers
// ---------------------------------------------------------------------------
__device__ __forceinline__ uint32_t smem_u32(const void* p) {
    uint32_t a;
    asm("{ .reg .u64 t; cvta.to.shared.u64 t, %1; cvt.u32.u64 %0, t; }"
        : "=r"(a) : "l"(p));
    return a;
}
#define CP16(dst, src) \
    asm volatile("cp.async.cg.shared.global [%0], [%1], 16;" \
                 :: "r"(dst), "l"(src) : "memory")

#define MMA_F16(cc, a, b)                                                     \
    asm volatile("mma.sync.aligned.m16n8k16.row.col.f32.f16.f16.f32 "        \
        "{%0,%1,%2,%3}, {%4,%5,%6,%7}, {%8,%9}, {%0,%1,%2,%3};"              \
        : "+f"((cc)[0]), "+f"((cc)[1]), "+f"((cc)[2]), "+f"((cc)[3])         \
        : "r"((a)[0]), "r"((a)[1]), "r"((a)[2]), "r"((a)[3]),                \
          "r"((b)[0]), "r"((b)[1]))

#define LDSM_X4(r0, r1, r2, r3, addr)                                        \
    asm volatile("ldmatrix.sync.aligned.m8n8.x4.shared.b16 {%0,%1,%2,%3}, [%4];" \
        : "=r"(r0), "=r"(r1), "=r"(r2), "=r"(r3) : "r"(addr))

// ---------------------------------------------------------------------------
// Kernel 1: weight norms / exponents; resets fixup counter
// ---------------------------------------------------------------------------
__global__ void prep_w_kernel(const float* __restrict__ W,
                              const float* __restrict__ p,
                              const float* __restrict__ q) {
    __shared__ float red[256];
    int c = blockIdx.x, t = threadIdx.x;
    if (blockIdx.x == 0 && t == 0) g_fix_cnt = 0;
    float s = 0.0f;
    for (int k = t; k < KK; k += 256) {
        float w = W[k * Co + c];
        s = fmaf(w, w, s);
    }
    red[t] = s; __syncthreads();
    for (int o = 128; o > 0; o >>= 1) {
        if (t < o) red[t] += red[t + o];
        __syncthreads();
    }
    if (t == 0) {
        float qq = q[0] * q[0] * 0.1f;
        g_ws[c] = 1.0f / (sqrtf(red[0]) + qq);
        g_ae[c] = p[c] * p[c] * 0.01f;
    }
}

// ---------------------------------------------------------------------------
// Kernel 1b: split W -> fp16 hi/lo in [n][k] + fp32 transpose
// ---------------------------------------------------------------------------
__global__ void split_w_kernel(const float* __restrict__ W) {
    int k = blockIdx.x, n = threadIdx.x;
    float w = W[k * Co + n];
    __half h = __float2half_rn(w);
    __half l = __float2half_rn(w - __half2float(h));
    g_Bh[n * KK + k] = h;
    g_Bl[n * KK + k] = l;
    g_WT[n * KK + k] = w;
}

// ---------------------------------------------------------------------------
// Kernel 2: warp per pixel: split x -> fp16 hi/lo AND sum of squares
// ---------------------------------------------------------------------------
__global__ void split_x_sumsq_kernel(const float* __restrict__ x) {
    int pix  = blockIdx.x * 8 + (threadIdx.x >> 5);
    int lane = threadIdx.x & 31;
    size_t base = (size_t)pix * Cc + lane * 4;
    float4 v = *reinterpret_cast<const float4*>(x + base);

    __half hx = __float2half_rn(v.x), hy = __float2half_rn(v.y);
    __half hz = __float2half_rn(v.z), hw = __float2half_rn(v.w);
    __half lx = __float2half_rn(v.x - __half2float(hx));
    __half ly = __float2half_rn(v.y - __half2float(hy));
    __half lz = __float2half_rn(v.z - __half2float(hz));
    __half lw = __float2half_rn(v.w - __half2float(hw));

    *reinterpret_cast<__half2*>(g_Ah + base)     = __halves2half2(hx, hy);
    *reinterpret_cast<__half2*>(g_Ah + base + 2) = __halves2half2(hz, hw);
    *reinterpret_cast<__half2*>(g_Al + base)     = __halves2half2(lx, ly);
    *reinterpret_cast<__half2*>(g_Al + base + 2) = __halves2half2(lz, lw);

    float s = v.x * v.x + v.y * v.y + v.z * v.z + v.w * v.w;
    #pragma unroll
    for (int o = 16; o > 0; o >>= 1) s += __shfl_xor_sync(0xffffffffu, s, o);
    if (lane == 0) g_s[pix] = s;
}

// ---------------------------------------------------------------------------
// Kernel 3: 3x3 window sum -> inverse patch norm
// ---------------------------------------------------------------------------
__global__ void xnorm_kernel(const float* __restrict__ q) {
    int idx = blockIdx.x * 256 + threadIdx.x;
    if (idx >= MM) return;
    int n = idx / (Ho * Wo);
    int r = idx % (Ho * Wo);
    int h = r / Wo;
    int w = r % Wo;
    const float* sp = g_s + ((size_t)n * Hh + h) * Wd + w;
    float sum = 0.0f;
    #pragma unroll
    for (int ky = 0; ky < 3; ++ky)
        sum += sp[ky * Wd] + sp[ky * Wd + 1] + sp[ky * Wd + 2];
    float qq = q[0] * q[0] * 0.1f;
    g_xni[idx] = 1.0f / (sqrtf(sum) + qq);
}

// ---------------------------------------------------------------------------
// Kernel 4: fp16 3-pass split GEMM, ldmatrix fragments, K-stage 32,
// 3-deep cp.async pipeline, 2 CTAs/SM. 8 warps (4M x 2N), warp tile 32x64.
// smem per stage: A 128 rows x 128B (hi ch0-3 | lo ch4-7), B same. 32KB.
// ---------------------------------------------------------------------------
#define NST 36                  // KK/32
#define RG_A 0
#define RG_B 16384
#define STG 32768
#define SMEM_DYN (3 * STG)      // 98304
#define LISTCAP 8192

extern __shared__ char dsm[];

__global__ void __launch_bounds__(256, 2)
conv_hmma_kernel(const float* __restrict__ bias, float* __restrict__ out) {
    __shared__ float s_ws[128], s_ae[128], s_bi[128];
    __shared__ int   s_rb[128];
    __shared__ uint32_t s_cnt, s_base;

    const uint32_t sbase = smem_u32(dsm);
    const int t    = threadIdx.x;
    const int w    = t >> 5;
    const int lane = t & 31;
    const int gid  = lane >> 2;
    const int tig  = lane & 3;
    const int m0   = blockIdx.x * 128;
    const int n0   = blockIdx.y * 128;

    if (t < 128) {
        int m = m0 + t;
        int base = 0;
        if (m < MM) {
            int n = m / (Ho * Wo);
            int r = m % (Ho * Wo);
            int h = r / Wo;
            int ww = r % Wo;
            base = ((n * Hh + h) * Wd + ww) * Cc;
        }
        s_rb[t] = base;
        s_ws[t] = g_ws[n0 + t];
        s_ae[t] = g_ae[n0 + t];
        s_bi[t] = bias[n0 + t];
    }
    if (t == 0) s_cnt = 0;
    __syncthreads();

    // staging roles: thread -> row (0..127), half (0=hi chunks0-3, 1=lo 4-7)
    const int srow  = t >> 1;
    const int shalf = t & 1;
    const int abase = s_rb[srow];
    const int swr   = srow & 7;

    // warp tile
    const int wmo = (w & 3) * 32;
    const int wno = (w >> 2) * 64;

    // ldmatrix per-thread invariants
    const uint32_t sw    = lane & 7;
    const uint32_t aRow0 = (uint32_t)(wmo + (lane & 15)) * 128u;      // mi=0
    const uint32_t aRow1 = aRow0 + 16u * 128u;                        // mi=1
    const uint32_t aCsel = (lane >> 4);            // chunk offset 0/1 within kstep
    const uint32_t bRowB = (uint32_t)(wno + ((lane >> 4) << 3) + (lane & 7)) * 128u;
    const uint32_t bCsel = (lane >> 3) & 1;

    float c[2][8][4];
    #pragma unroll
    for (int mi = 0; mi < 2; ++mi)
        #pragma unroll
        for (int ni = 0; ni < 8; ++ni)
            #pragma unroll
            for (int j = 0; j < 4; ++j) c[mi][ni][j] = 0.0f;

    #define STAGE_CP(s) do {                                                  \
        uint32_t bb = sbase + (uint32_t)((s) % 3) * STG;                      \
        int g  = (s) >> 2;                                                    \
        int cb = ((s) & 3) * 32;                                              \
        int ky = g / 3, kx = g - ky * 3;                                      \
        size_t axoff = (size_t)abase + (ky * Wd + kx) * Cc + cb;              \
        size_t bxoff = (size_t)(n0 + srow) * KK + (s) * 32;                   \
        const __half* pA = shalf ? (g_Al + axoff) : (g_Ah + axoff);           \
        const __half* pB = shalf ? (g_Bl + bxoff) : (g_Bh + bxoff);           \
        _Pragma("unroll")                                                     \
        for (int i = 0; i < 4; ++i) {                                         \
            uint32_t cch = (uint32_t)(shalf * 4 + i);                         \
            uint32_t dof = (uint32_t)srow * 128u + ((cch ^ (uint32_t)swr) << 4); \
            CP16(bb + RG_A + dof, pA + i * 8);                                \
            CP16(bb + RG_B + dof, pB + i * 8);                                \
        }                                                                     \
        asm volatile("cp.async.commit_group;" ::: "memory");                  \
    } while (0)

    STAGE_CP(0);
    STAGE_CP(1);

    for (int s = 0; s < NST; ++s) {
        if (s + 1 < NST)
            asm volatile("cp.async.wait_group 1;" ::: "memory");
        else
            asm volatile("cp.async.wait_group 0;" ::: "memory");
        __syncthreads();
        if (s + 2 < NST) STAGE_CP(s + 2);

        const uint32_t bb = sbase + (uint32_t)(s % 3) * STG;
        const uint32_t aB = bb + RG_A;
        const uint32_t bB = bb + RG_B;

        #pragma unroll
        for (int ks = 0; ks < 2; ++ks) {
            const uint32_t cHiA = (uint32_t)(2 * ks) + aCsel;       // 0..3
            const uint32_t cHiB = (uint32_t)(2 * ks) + bCsel;
            const uint32_t offHiA = (cHiA ^ sw) << 4;
            const uint32_t offLoA = ((cHiA + 4u) ^ sw) << 4;
            const uint32_t offHiB = (cHiB ^ sw) << 4;
            const uint32_t offLoB = ((cHiB + 4u) ^ sw) << 4;

            uint32_t ah[2][4], al[2][4], bv[8][2];

            // A hi
            LDSM_X4(ah[0][0], ah[0][1], ah[0][2], ah[0][3], aB + aRow0 + offHiA);
            LDSM_X4(ah[1][0], ah[1][1], ah[1][2], ah[1][3], aB + aRow1 + offHiA);
            // B hi (4 x4 ops cover 8 ni)
            #pragma unroll
            for (int pp = 0; pp < 4; ++pp) {
                LDSM_X4(bv[2*pp][0], bv[2*pp][1], bv[2*pp+1][0], bv[2*pp+1][1],
                        bB + bRowB + (uint32_t)(pp * 16 * 128) + offHiB);
            }
            // pass 1: Ah * Bh
            #pragma unroll
            for (int mi = 0; mi < 2; ++mi)
                #pragma unroll
                for (int ni = 0; ni < 8; ++ni) MMA_F16(c[mi][ni], ah[mi], bv[ni]);

            // A lo
            LDSM_X4(al[0][0], al[0][1], al[0][2], al[0][3], aB + aRow0 + offLoA);
            LDSM_X4(al[1][0], al[1][1], al[1][2], al[1][3], aB + aRow1 + offLoA);
            // pass 2: Al * Bh
            #pragma unroll
            for (int mi = 0; mi < 2; ++mi)
                #pragma unroll
                for (int ni = 0; ni < 8; ++ni) MMA_F16(c[mi][ni], al[mi], bv[ni]);

            // B lo (reuse bv)
            #pragma unroll
            for (int pp = 0; pp < 4; ++pp) {
                LDSM_X4(bv[2*pp][0], bv[2*pp][1], bv[2*pp+1][0], bv[2*pp+1][1],
                        bB + bRowB + (uint32_t)(pp * 16 * 128) + offLoB);
            }
            // pass 3: Ah * Bl
            #pragma unroll
            for (int mi = 0; mi < 2; ++mi)
                #pragma unroll
                for (int ni = 0; ni < 8; ++ni) MMA_F16(c[mi][ni], ah[mi], bv[ni]);
        }
        __syncthreads();
    }

    // ---- fused epilogue with candidate flagging ----
    uint32_t* s_list = (uint32_t*)dsm;   // stage buffers dead

    #pragma unroll
    for (int mi = 0; mi < 2; ++mi) {
        int r0 = m0 + wmo + mi * 16 + gid;
        int r1 = r0 + 8;
        bool v0 = (r0 < MM), v1 = (r1 < MM);
        float xn0 = v0 ? g_xni[r0] : 0.0f;
        float xn1 = v1 ? g_xni[r1] : 0.0f;
        #pragma unroll
        for (int ni = 0; ni < 8; ++ni) {
            int cl = wno + ni * 8 + 2 * tig;
            float bi0 = s_bi[cl], bi1 = s_bi[cl + 1];
            float ws0 = s_ws[cl], ws1 = s_ws[cl + 1];
            float ae0 = s_ae[cl], ae1 = s_ae[cl + 1];

            float f00 = c[mi][ni][0] + bi0;
            float f01 = c[mi][ni][1] + bi1;
            float f10 = c[mi][ni][2] + bi0;
            float f11 = c[mi][ni][3] + bi1;

            float y00 = f00 * xn0 * ws0;
            float y01 = f01 * xn0 * ws1;
            float y10 = f10 * xn1 * ws0;
            float y11 = f11 * xn1 * ws1;

            if (v0 && fabsf(y00) < TAU) {
                uint32_t i = atomicAdd(&s_cnt, 1u);
                if (i < LISTCAP) s_list[i] = ((uint32_t)r0 << 8) | (uint32_t)(n0 + cl);
            }
            if (v0 && fabsf(y01) < TAU) {
                uint32_t i = atomicAdd(&s_cnt, 1u);
                if (i < LISTCAP) s_list[i] = ((uint32_t)r0 << 8) | (uint32_t)(n0 + cl + 1);
            }
            if (v1 && fabsf(y10) < TAU) {
                uint32_t i = atomicAdd(&s_cnt, 1u);
                if (i < LISTCAP) s_list[i] = ((uint32_t)r1 << 8) | (uint32_t)(n0 + cl);
            }
            if (v1 && fabsf(y11) < TAU) {
                uint32_t i = atomicAdd(&s_cnt, 1u);
                if (i < LISTCAP) s_list[i] = ((uint32_t)r1 << 8) | (uint32_t)(n0 + cl + 1);
            }

            float a00 = fabsf(y00) + 1e-12f;
            float a01 = fabsf(y01) + 1e-12f;
            float a10 = fabsf(y10) + 1e-12f;
            float a11 = fabsf(y11) + 1e-12f;

            float o00 = copysignf(__expf(ae0 * __logf(a00)), f00);
            float o01 = copysignf(__expf(ae1 * __logf(a01)), f01);
            float o10 = copysignf(__expf(ae0 * __logf(a10)), f10);
            float o11 = copysignf(__expf(ae1 * __logf(a11)), f11);

            if (v0)
                *reinterpret_cast<float2*>(out + (size_t)r0 * Co + n0 + cl) =
                    make_float2(o00, o01);
            if (v1)
                *reinterpret_cast<float2*>(out + (size_t)r1 * Co + n0 + cl) =
                    make_float2(o10, o11);
        }
    }

    // flush candidate list to global
    __syncthreads();
    if (t == 0) {
        uint32_t cc = s_cnt < LISTCAP ? s_cnt : LISTCAP;
        s_cnt = cc;
        s_base = atomicAdd(&g_fix_cnt, cc);
    }
    __syncthreads();
    for (uint32_t i = t; i < s_cnt; i += 256) {
        uint32_t gidx = s_base + i;
        if (gidx < FIXCAP) g_fix_list[gidx] = s_list[i];
    }
    #undef STAGE_CP
}

// ---------------------------------------------------------------------------
// Kernel 5: exact fp32 recompute of flagged elements (warp per candidate)
// ---------------------------------------------------------------------------
__global__ void fixup_kernel(const float* __restrict__ x,
                             const float* __restrict__ bias,
                             float* __restrict__ out) {
    uint32_t total = g_fix_cnt;
    if (total > FIXCAP) total = FIXCAP;
    uint32_t wid   = (blockIdx.x * blockDim.x + threadIdx.x) >> 5;
    uint32_t nwarp = (gridDim.x * blockDim.x) >> 5;
    int lane = threadIdx.x & 31;

    for (uint32_t e = wid; e < total; e += nwarp) {
        uint32_t enc = g_fix_list[e];
        int m  = enc >> 8;
        int co = enc & 255;
        int n = m / (Ho * Wo);
        int r = m % (Ho * Wo);
        int h = r / Wo;
        int ww = r % Wo;
        int base = ((n * Hh + h) * Wd + ww) * Cc;

        float sum = 0.0f;
        #pragma unroll
        for (int g = 0; g < 9; ++g) {
            int ky = g / 3, kx = g - ky * 3;
            const float* xp = x + base + (ky * Wd + kx) * Cc;
            const float* wp = g_WT + (size_t)co * KK + g * 128;
            #pragma unroll
            for (int ci = 0; ci < 4; ++ci) {
                int cch = ci * 32 + lane;
                sum = fmaf(xp[cch], wp[cch], sum);
            }
        }
        #pragma unroll
        for (int o = 16; o > 0; o >>= 1)
            sum += __shfl_xor_sync(0xffffffffu, sum, o);

        if (lane == 0) {
            float f  = sum + bias[co];
            float y  = f * g_xni[m] * g_ws[co];
            float ay = fabsf(y) + 1e-12f;
            float rr = __expf(g_ae[co] * __logf(ay));
            out[(size_t)m * Co + co] = copysignf(rr, f);
        }
    }
}

// ---------------------------------------------------------------------------
extern "C" void kernel_launch(void* const* d_in, const int* in_sizes, int n_in,
                              void* d_out, int out_size) {
    const float* x = (const float*)d_in[0];
    const float* W = (const float*)d_in[1];
    const float* b = (const float*)d_in[2];
    const float* p = (const float*)d_in[3];
    const float* q = (const float*)d_in[4];
    float* out = (float*)d_out;

    prep_w_kernel<<<Co, 256>>>(W, p, q);
    split_w_kernel<<<KK, 256>>>(W);
    split_x_sumsq_kernel<<<PIX / 8, 256>>>(x);
    xnorm_kernel<<<(MM + 255) / 256, 256>>>(q);

    static bool attr_set = false;
    if (!attr_set) {
        cudaFuncSetAttribute(conv_hmma_kernel,
                             cudaFuncAttributeMaxDynamicSharedMemorySize, SMEM_DYN);
        attr_set = true;
    }
    dim3 grid((MM + 127) / 128, Co / 128);
    conv_hmma_kernel<<<grid, 256, SMEM_DYN>>>(b, out);

    fixup_kernel<<<512, 256>>>(x, b, out);
}

// round 6
// speedup vs baseline: 2.4240x; 2.4240x over previous
#include <cuda_runtime.h>
#include <cuda_fp16.h>
#include <cstdint>
#include <math.h>

// ---------------------------------------------------------------------------
// Problem constants
// ---------------------------------------------------------------------------
#define Nn 16
#define Hh 112
#define Wd 112
#define Cc 128
#define Ho 110
#define Wo 110
#define Co 256
#define KK 1152                 // 3*3*128
#define MM (Nn*Ho*Wo)           // 193600
#define PIX (Nn*Hh*Wd)          // 200704
#define XELT (PIX*Cc)           // 25,690,112
#define FIXCAP (1u << 21)
#define TAU 5e-5f               // |y| threshold for exact fp32 recompute

// ---------------------------------------------------------------------------
// Scratch (device globals; no allocations allowed)
// ---------------------------------------------------------------------------
__device__ float g_s[PIX];
__device__ float g_xni[MM];
__device__ float g_ws[Co];
__device__ float g_ae[Co];
__device__ __half g_Ah[XELT];        // x hi (fp16)
__device__ __half g_Bh[Co * KK];     // W hi, [n][k]
__device__ float  g_WT[Co * KK];     // W fp32 [n][k] (fixup)
__device__ uint32_t g_fix_list[FIXCAP];
__device__ uint32_t g_fix_cnt;

// ---------------------------------------------------------------------------
// Helpers
// ---------------------------------------------------------------------------
__device__ __forceinline__ uint32_t smem_u32(const void* p) {
    uint32_t a;
    asm("{ .reg .u64 t; cvta.to.shared.u64 t, %1; cvt.u32.u64 %0, t; }"
        : "=r"(a) : "l"(p));
    return a;
}
#define CP16(dst, src) \
    asm volatile("cp.async.cg.shared.global [%0], [%1], 16;" \
                 :: "r"(dst), "l"(src) : "memory")

#define MMA_F16(cc, a, b)                                                     \
    asm volatile("mma.sync.aligned.m16n8k16.row.col.f32.f16.f16.f32 "        \
        "{%0,%1,%2,%3}, {%4,%5,%6,%7}, {%8,%9}, {%0,%1,%2,%3};"              \
        : "+f"((cc)[0]), "+f"((cc)[1]), "+f"((cc)[2]), "+f"((cc)[3])         \
        : "r"((a)[0]), "r"((a)[1]), "r"((a)[2]), "r"((a)[3]),                \
          "r"((b)[0]), "r"((b)[1]))

#define LDSM_X4(r0, r1, r2, r3, addr)                                        \
    asm volatile("ldmatrix.sync.aligned.m8n8.x4.shared.b16 {%0,%1,%2,%3}, [%4];" \
        : "=r"(r0), "=r"(r1), "=r"(r2), "=r"(r3) : "r"(addr))

// ---------------------------------------------------------------------------
// Kernel 1: weight norms / exponents; resets fixup counter
// ---------------------------------------------------------------------------
__global__ void prep_w_kernel(const float* __restrict__ W,
                              const float* __restrict__ p,
                              const float* __restrict__ q) {
    __shared__ float red[256];
    int c = blockIdx.x, t = threadIdx.x;
    if (blockIdx.x == 0 && t == 0) g_fix_cnt = 0;
    float s = 0.0f;
    for (int k = t; k < KK; k += 256) {
        float w = W[k * Co + c];
        s = fmaf(w, w, s);
    }
    red[t] = s; __syncthreads();
    for (int o = 128; o > 0; o >>= 1) {
        if (t < o) red[t] += red[t + o];
        __syncthreads();
    }
    if (t == 0) {
        float qq = q[0] * q[0] * 0.1f;
        g_ws[c] = 1.0f / (sqrtf(red[0]) + qq);
        g_ae[c] = p[c] * p[c] * 0.01f;
    }
}

// ---------------------------------------------------------------------------
// Kernel 1b: W -> fp16 hi in [n][k] + fp32 transpose (for fixup)
// ---------------------------------------------------------------------------
__global__ void split_w_kernel(const float* __restrict__ W) {
    int k = blockIdx.x, n = threadIdx.x;
    float w = W[k * Co + n];
    g_Bh[n * KK + k] = __float2half_rn(w);
    g_WT[n * KK + k] = w;
}

// ---------------------------------------------------------------------------
// Kernel 2: warp per pixel: x -> fp16 hi AND sum of squares
// ---------------------------------------------------------------------------
__global__ void split_x_sumsq_kernel(const float* __restrict__ x) {
    int pix  = blockIdx.x * 8 + (threadIdx.x >> 5);
    int lane = threadIdx.x & 31;
    size_t base = (size_t)pix * Cc + lane * 4;
    float4 v = *reinterpret_cast<const float4*>(x + base);

    __half2 h01 = __halves2half2(__float2half_rn(v.x), __float2half_rn(v.y));
    __half2 h23 = __halves2half2(__float2half_rn(v.z), __float2half_rn(v.w));
    *reinterpret_cast<__half2*>(g_Ah + base)     = h01;
    *reinterpret_cast<__half2*>(g_Ah + base + 2) = h23;

    float s = v.x * v.x + v.y * v.y + v.z * v.z + v.w * v.w;
    #pragma unroll
    for (int o = 16; o > 0; o >>= 1) s += __shfl_xor_sync(0xffffffffu, s, o);
    if (lane == 0) g_s[pix] = s;
}

// ---------------------------------------------------------------------------
// Kernel 3: 3x3 window sum -> inverse patch norm
// ---------------------------------------------------------------------------
__global__ void xnorm_kernel(const float* __restrict__ q) {
    int idx = blockIdx.x * 256 + threadIdx.x;
    if (idx >= MM) return;
    int n = idx / (Ho * Wo);
    int r = idx % (Ho * Wo);
    int h = r / Wo;
    int w = r % Wo;
    const float* sp = g_s + ((size_t)n * Hh + h) * Wd + w;
    float sum = 0.0f;
    #pragma unroll
    for (int ky = 0; ky < 3; ++ky)
        sum += sp[ky * Wd] + sp[ky * Wd + 1] + sp[ky * Wd + 2];
    float qq = q[0] * q[0] * 0.1f;
    g_xni[idx] = 1.0f / (sqrtf(sum) + qq);
}

// ---------------------------------------------------------------------------
// Kernel 4: single-pass fp16 implicit GEMM (hi*hi), ldmatrix fragments,
// K-stage 64, 3-deep cp.async pipeline, 2 CTAs/SM, 8 warps (4M x 2N).
// Stage: A 128 rows x 128B (8 chunks, XOR-8 swizzle) = 16KB, B same. 32KB.
// ---------------------------------------------------------------------------
#define NST 18                  // KK/64
#define RG_A 0
#define RG_B 16384
#define STG 32768
#define SMEM_DYN (3 * STG)      // 98304
#define LISTCAP 8192

extern __shared__ char dsm[];

__global__ void __launch_bounds__(256, 2)
conv_hmma_kernel(const float* __restrict__ bias, float* __restrict__ out) {
    __shared__ float s_ws[128], s_ae[128], s_bi[128];
    __shared__ int   s_rb[128];
    __shared__ uint32_t s_cnt, s_base;

    const uint32_t sbase = smem_u32(dsm);
    const int t    = threadIdx.x;
    const int w    = t >> 5;
    const int lane = t & 31;
    const int gid  = lane >> 2;
    const int tig  = lane & 3;
    const int m0   = blockIdx.x * 128;
    const int n0   = blockIdx.y * 128;

    if (t < 128) {
        int m = m0 + t;
        int base = 0;
        if (m < MM) {
            int n = m / (Ho * Wo);
            int r = m % (Ho * Wo);
            int h = r / Wo;
            int ww = r % Wo;
            base = ((n * Hh + h) * Wd + ww) * Cc;
        }
        s_rb[t] = base;
        s_ws[t] = g_ws[n0 + t];
        s_ae[t] = g_ae[n0 + t];
        s_bi[t] = bias[n0 + t];
    }
    if (t == 0) s_cnt = 0;
    __syncthreads();

    // staging roles: thread -> row (0..127), chunk group of 4
    const int srow  = t >> 1;
    const int sgrp  = (t & 1) * 4;
    const int abase = s_rb[srow];
    const int swr   = srow & 7;

    // warp tile
    const int wmo = (w & 3) * 32;
    const int wno = (w >> 2) * 64;

    // ldmatrix per-thread invariants (mapping proven in R5)
    const uint32_t sw    = lane & 7;
    const uint32_t aRow0 = (uint32_t)(wmo + (lane & 15)) * 128u;
    const uint32_t aRow1 = aRow0 + 16u * 128u;
    const uint32_t aCsel = (lane >> 4);
    const uint32_t bRowB = (uint32_t)(wno + ((lane >> 4) << 3) + (lane & 7)) * 128u;
    const uint32_t bCsel = (lane >> 3) & 1;

    float c[2][8][4];
    #pragma unroll
    for (int mi = 0; mi < 2; ++mi)
        #pragma unroll
        for (int ni = 0; ni < 8; ++ni)
            #pragma unroll
            for (int j = 0; j < 4; ++j) c[mi][ni][j] = 0.0f;

    #define STAGE_CP(s) do {                                                  \
        uint32_t bb = sbase + (uint32_t)((s) % 3) * STG;                      \
        int g  = (s) >> 1;                                                    \
        int cb = ((s) & 1) * 64;                                              \
        int ky = g / 3, kx = g - ky * 3;                                      \
        size_t axoff = (size_t)abase + (ky * Wd + kx) * Cc + cb;              \
        size_t bxoff = (size_t)(n0 + srow) * KK + (size_t)(s) * 64;           \
        _Pragma("unroll")                                                     \
        for (int i = 0; i < 4; ++i) {                                         \
            uint32_t cch = (uint32_t)(sgrp + i);                              \
            uint32_t dof = (uint32_t)srow * 128u + ((cch ^ (uint32_t)swr) << 4); \
            CP16(bb + RG_A + dof, g_Ah + axoff + cch * 8);                    \
            CP16(bb + RG_B + dof, g_Bh + bxoff + cch * 8);                    \
        }                                                                     \
        asm volatile("cp.async.commit_group;" ::: "memory");                  \
    } while (0)

    STAGE_CP(0);
    STAGE_CP(1);

    for (int s = 0; s < NST; ++s) {
        if (s + 1 < NST)
            asm volatile("cp.async.wait_group 1;" ::: "memory");
        else
            asm volatile("cp.async.wait_group 0;" ::: "memory");
        __syncthreads();
        if (s + 2 < NST) STAGE_CP(s + 2);

        const uint32_t aB = sbase + (uint32_t)(s % 3) * STG + RG_A;
        const uint32_t bB = sbase + (uint32_t)(s % 3) * STG + RG_B;

        #pragma unroll
        for (int ks = 0; ks < 4; ++ks) {
            const uint32_t offA = (((uint32_t)(2 * ks) + aCsel) ^ sw) << 4;
            const uint32_t offB = (((uint32_t)(2 * ks) + bCsel) ^ sw) << 4;

            uint32_t ah[2][4], bv[8][2];

            LDSM_X4(ah[0][0], ah[0][1], ah[0][2], ah[0][3], aB + aRow0 + offA);
            LDSM_X4(ah[1][0], ah[1][1], ah[1][2], ah[1][3], aB + aRow1 + offA);
            #pragma unroll
            for (int pp = 0; pp < 4; ++pp) {
                LDSM_X4(bv[2*pp][0], bv[2*pp][1], bv[2*pp+1][0], bv[2*pp+1][1],
                        bB + bRowB + (uint32_t)(pp * 16 * 128) + offB);
            }
            #pragma unroll
            for (int mi = 0; mi < 2; ++mi)
                #pragma unroll
                for (int ni = 0; ni < 8; ++ni) MMA_F16(c[mi][ni], ah[mi], bv[ni]);
        }
        __syncthreads();
    }

    // ---- fused epilogue with candidate flagging ----
    uint32_t* s_list = (uint32_t*)dsm;   // stage buffers dead

    #pragma unroll
    for (int mi = 0; mi < 2; ++mi) {
        int r0 = m0 + wmo + mi * 16 + gid;
        int r1 = r0 + 8;
        bool v0 = (r0 < MM), v1 = (r1 < MM);
        float xn0 = v0 ? g_xni[r0] : 0.0f;
        float xn1 = v1 ? g_xni[r1] : 0.0f;
        #pragma unroll
        for (int ni = 0; ni < 8; ++ni) {
            int cl = wno + ni * 8 + 2 * tig;
            float bi0 = s_bi[cl], bi1 = s_bi[cl + 1];
            float ws0 = s_ws[cl], ws1 = s_ws[cl + 1];
            float ae0 = s_ae[cl], ae1 = s_ae[cl + 1];

            float f00 = c[mi][ni][0] + bi0;
            float f01 = c[mi][ni][1] + bi1;
            float f10 = c[mi][ni][2] + bi0;
            float f11 = c[mi][ni][3] + bi1;

            float y00 = f00 * xn0 * ws0;
            float y01 = f01 * xn0 * ws1;
            float y10 = f10 * xn1 * ws0;
            float y11 = f11 * xn1 * ws1;

            if (v0 && fabsf(y00) < TAU) {
                uint32_t i = atomicAdd(&s_cnt, 1u);
                if (i < LISTCAP) s_list[i] = ((uint32_t)r0 << 8) | (uint32_t)(n0 + cl);
            }
            if (v0 && fabsf(y01) < TAU) {
                uint32_t i = atomicAdd(&s_cnt, 1u);
                if (i < LISTCAP) s_list[i] = ((uint32_t)r0 << 8) | (uint32_t)(n0 + cl + 1);
            }
            if (v1 && fabsf(y10) < TAU) {
                uint32_t i = atomicAdd(&s_cnt, 1u);
                if (i < LISTCAP) s_list[i] = ((uint32_t)r1 << 8) | (uint32_t)(n0 + cl);
            }
            if (v1 && fabsf(y11) < TAU) {
                uint32_t i = atomicAdd(&s_cnt, 1u);
                if (i < LISTCAP) s_list[i] = ((uint32_t)r1 << 8) | (uint32_t)(n0 + cl + 1);
            }

            float a00 = fabsf(y00) + 1e-12f;
            float a01 = fabsf(y01) + 1e-12f;
            float a10 = fabsf(y10) + 1e-12f;
            float a11 = fabsf(y11) + 1e-12f;

            float o00 = copysignf(__expf(ae0 * __logf(a00)), f00);
            float o01 = copysignf(__expf(ae1 * __logf(a01)), f01);
            float o10 = copysignf(__expf(ae0 * __logf(a10)), f10);
            float o11 = copysignf(__expf(ae1 * __logf(a11)), f11);

            if (v0)
                *reinterpret_cast<float2*>(out + (size_t)r0 * Co + n0 + cl) =
                    make_float2(o00, o01);
            if (v1)
                *reinterpret_cast<float2*>(out + (size_t)r1 * Co + n0 + cl) =
                    make_float2(o10, o11);
        }
    }

    // flush candidate list to global
    __syncthreads();
    if (t == 0) {
        uint32_t cc = s_cnt < LISTCAP ? s_cnt : LISTCAP;
        s_cnt = cc;
        s_base = atomicAdd(&g_fix_cnt, cc);
    }
    __syncthreads();
    for (uint32_t i = t; i < s_cnt; i += 256) {
        uint32_t gidx = s_base + i;
        if (gidx < FIXCAP) g_fix_list[gidx] = s_list[i];
    }
    #undef STAGE_CP
}

// ---------------------------------------------------------------------------
// Kernel 5: exact fp32 recompute of flagged elements (warp per candidate)
// ---------------------------------------------------------------------------
__global__ void fixup_kernel(const float* __restrict__ x,
                             const float* __restrict__ bias,
                             float* __restrict__ out) {
    uint32_t total = g_fix_cnt;
    if (total > FIXCAP) total = FIXCAP;
    uint32_t wid   = (blockIdx.x * blockDim.x + threadIdx.x) >> 5;
    uint32_t nwarp = (gridDim.x * blockDim.x) >> 5;
    int lane = threadIdx.x & 31;

    for (uint32_t e = wid; e < total; e += nwarp) {
        uint32_t enc = g_fix_list[e];
        int m  = enc >> 8;
        int co = enc & 255;
        int n = m / (Ho * Wo);
        int r = m % (Ho * Wo);
        int h = r / Wo;
        int ww = r % Wo;
        int base = ((n * Hh + h) * Wd + ww) * Cc;

        float sum = 0.0f;
        #pragma unroll
        for (int g = 0; g < 9; ++g) {
            int ky = g / 3, kx = g - ky * 3;
            const float* xp = x + base + (ky * Wd + kx) * Cc;
            const float* wp = g_WT + (size_t)co * KK + g * 128;
            #pragma unroll
            for (int ci = 0; ci < 4; ++ci) {
                int cch = ci * 32 + lane;
                sum = fmaf(xp[cch], wp[cch], sum);
            }
        }
        #pragma unroll
        for (int o = 16; o > 0; o >>= 1)
            sum += __shfl_xor_sync(0xffffffffu, sum, o);

        if (lane == 0) {
            float f  = sum + bias[co];
            float y  = f * g_xni[m] * g_ws[co];
            float ay = fabsf(y) + 1e-12f;
            float rr = __expf(g_ae[co] * __logf(ay));
            out[(size_t)m * Co + co] = copysignf(rr, f);
        }
    }
}

// ---------------------------------------------------------------------------
extern "C" void kernel_launch(void* const* d_in, const int* in_sizes, int n_in,
                              void* d_out, int out_size) {
    const float* x = (const float*)d_in[0];
    const float* W = (const float*)d_in[1];
    const float* b = (const float*)d_in[2];
    const float* p = (const float*)d_in[3];
    const float* q = (const float*)d_in[4];
    float* out = (float*)d_out;

    prep_w_kernel<<<Co, 256>>>(W, p, q);
    split_w_kernel<<<KK, 256>>>(W);
    split_x_sumsq_kernel<<<PIX / 8, 256>>>(x);
    xnorm_kernel<<<(MM + 255) / 256, 256>>>(q);

    static bool attr_set = false;
    if (!attr_set) {
        cudaFuncSetAttribute(conv_hmma_kernel,
                             cudaFuncAttributeMaxDynamicSharedMemorySize, SMEM_DYN);
        attr_set = true;
    }
    dim3 grid((MM + 127) / 128, Co / 128);
    conv_hmma_kernel<<<grid, 256, SMEM_DYN>>>(b, out);

    fixup_kernel<<<512, 256>>>(x, b, out);
}